// round 3
// baseline (speedup 1.0000x reference)
#include <cuda_runtime.h>
#include <cuda_fp16.h>
#include <cstdint>

// ---------------- PTX helpers (family-agnostic: sm_80-level) ----------------

__device__ __forceinline__ uint32_t smem_u32(const void* p) {
    uint32_t a;
    asm("{ .reg .u64 t; cvta.to.shared.u64 t, %1; cvt.u32.u64 %0, t; }" : "=r"(a) : "l"(p));
    return a;
}

#define LDSM_X4(r0,r1,r2,r3,addr) \
    asm volatile("ldmatrix.sync.aligned.m8n8.x4.shared.b16 {%0,%1,%2,%3}, [%4];" \
        : "=r"(r0),"=r"(r1),"=r"(r2),"=r"(r3) : "r"(addr))

#define MMA_16816(c,a,b0,b1) \
    asm volatile("mma.sync.aligned.m16n8k16.row.col.f32.f16.f16.f32 " \
        "{%0,%1,%2,%3}, {%4,%5,%6,%7}, {%8,%9}, {%0,%1,%2,%3};" \
        : "+f"((c)[0]),"+f"((c)[1]),"+f"((c)[2]),"+f"((c)[3]) \
        : "r"((a)[0]),"r"((a)[1]),"r"((a)[2]),"r"((a)[3]),"r"(b0),"r"(b1))

#define CP_ASYNC16(dst,src) \
    asm volatile("cp.async.cg.shared.global [%0], [%1], 16;" :: "r"(dst),"l"(src) : "memory")
#define CP_COMMIT() asm volatile("cp.async.commit_group;" ::: "memory")
#define CP_WAIT0()  asm volatile("cp.async.wait_group 0;" ::: "memory")

__device__ __forceinline__ uint32_t hmul2(uint32_t a, uint32_t b) {
    uint32_t d; asm("mul.rn.f16x2 %0, %1, %2;" : "=r"(d) : "r"(a), "r"(b)); return d;
}
__device__ __forceinline__ uint32_t packh2(float a, float b) {
    return (uint32_t)__half_as_ushort(__float2half_rn(a)) |
           ((uint32_t)__half_as_ushort(__float2half_rn(b)) << 16);
}
__device__ __forceinline__ uint32_t f2h2dup(float g) {
    uint32_t h = (uint32_t)__half_as_ushort(__float2half_rn(g));
    return h | (h << 16);
}

// ---------------- problem constants ----------------

static constexpr int TPB    = 256;
static constexpr int TILE_M = 128;
static constexpr int DIM    = 128;
static constexpr int NEXP   = 8;

// padded smem row strides (in halves / bytes)
static constexpr int LDH  = 136;   // X/W tiles: 136 halves = 272 B rows (conflict-free ldmatrix)
static constexpr int LDHB = 272;
static constexpr int LDS_AG = 24;  // Ag/Bg tiles: 24 halves = 48 B rows (conflict-free)

// smem layout (bytes)
static constexpr int OFF_XH   = 0;                      // 128 x 136 halves = 34816
static constexpr int OFF_WH   = 34816;                  // 128 x 136 halves = 34816
static constexpr int OFF_AG   = 69632;                  // 128 x 24 halves  = 6144 (gates f16, k-padded to 16)
static constexpr int OFF_BG   = 75776;                  // 128 x 24 halves  = 6144 (b^T f16, k-padded to 16)
static constexpr int OFF_GW   = 81920;                  // 4096 gate_W fp32
static constexpr int OFF_GM   = 86016;                  // 4096 masked gates fp32 [128][8]
static constexpr int OFF_PART = 90112;                  // 8192 gating partials [256][8]
static constexpr int SMEM_BYTES = 98304;                // 96 KB -> 2 CTAs/SM

// W pre-converted to f16, expert-major, same linear order as fp32 W
__device__ __align__(16) unsigned char g_Wh[NEXP * DIM * DIM * 2];

// ---------------- prepass: W fp32 -> f16 ----------------

__global__ void convert_w_kernel(const float* __restrict__ W) {
    int i = blockIdx.x * blockDim.x + threadIdx.x;     // 0..32767 float4s
    float4 v = ((const float4*)W)[i];
    ((uint2*)g_Wh)[i] = make_uint2(packh2(v.x, v.y), packh2(v.z, v.w));
}

// ---------------- main kernel ----------------

__global__ void __launch_bounds__(TPB, 2)
moe_f16_kernel(const float* __restrict__ x,
               const float* __restrict__ gW,
               const float* __restrict__ gb,
               const float* __restrict__ b,
               float* __restrict__ out)
{
    extern __shared__ char smem[];
    const uint32_t sb = smem_u32(smem);

    const int tid  = threadIdx.x;
    const int lane = tid & 31;
    const int wid  = tid >> 5;
    const int row  = tid & 127;       // token row within tile
    const int half = tid >> 7;        // K half for gating/X-load
    const long tbase = (long)blockIdx.x * TILE_M;

    // ---- issue cp.async for expert 0's W immediately (overlaps everything) ----
    {
        const char* src = (const char*)g_Wh;            // expert 0
        #pragma unroll
        for (int it = 0; it < 8; it++) {
            const int c = tid + it * TPB;               // 2048 16B chunks
            const uint32_t dst = sb + OFF_WH + (uint32_t)((c >> 4) * LDHB + (c & 15) * 16);
            CP_ASYNC16(dst, src + c * 16);
        }
        CP_COMMIT();
    }

    // ---- stage gate_W ----
    {
        float4* gws = (float4*)(smem + OFF_GW);
        const float4* g4 = (const float4*)gW;
        gws[tid] = g4[tid];                              // exactly 256 float4
    }

    // ---- stage Bg = b^T in f16, k-padded to 16 (zeros) ----
    if (tid < DIM) {
        const int f = tid;
        uint32_t* dst = (uint32_t*)(smem + OFF_BG + f * (LDS_AG * 2));
        float bv[NEXP];
        #pragma unroll
        for (int e = 0; e < NEXP; e++) bv[e] = __ldg(b + e * DIM + f);
        dst[0] = packh2(bv[0], bv[1]);
        dst[1] = packh2(bv[2], bv[3]);
        dst[2] = packh2(bv[4], bv[5]);
        dst[3] = packh2(bv[6], bv[7]);
        dst[4] = 0; dst[5] = 0; dst[6] = 0; dst[7] = 0;
    }

    // ---- load X rows (fp32 regs) and stage f16 X tile ----
    float4 xv[16];
    {
        const float4* xg = (const float4*)(x + (tbase + row) * DIM + half * 64);
        #pragma unroll
        for (int i = 0; i < 16; i++) xv[i] = __ldg(xg + i);
        #pragma unroll
        for (int i = 0; i < 16; i++) {
            const int col = half * 64 + i * 4;
            uint32_t* d = (uint32_t*)(smem + OFF_XH + row * LDHB + col * 2);
            d[0] = packh2(xv[i].x, xv[i].y);
            d[1] = packh2(xv[i].z, xv[i].w);
        }
    }
    __syncthreads();

    // ---- gating partial dots (each thread: 64 features of its row) ----
    {
        const float* gws = (const float*)(smem + OFF_GW);
        float* part = (float*)(smem + OFF_PART);
        #pragma unroll
        for (int e = 0; e < NEXP; e++) {
            const float4* ge = (const float4*)(gws + e * DIM) + half * 16;
            float s = 0.f;
            #pragma unroll
            for (int i = 0; i < 16; i++) {
                float4 g4 = ge[i];
                s += xv[i].x * g4.x + xv[i].y * g4.y + xv[i].z * g4.z + xv[i].w * g4.w;
            }
            part[(half * 128 + row) * NEXP + e] = s;
        }
    }
    __syncthreads();

    // ---- softmax + top-2; write masked gates (fp32) + Ag (full gates, f16) ----
    if (half == 0) {
        const float* part = (const float*)(smem + OFF_PART);
        float lg[NEXP];
        #pragma unroll
        for (int e = 0; e < NEXP; e++)
            lg[e] = part[row * NEXP + e] + part[(128 + row) * NEXP + e] + __ldg(gb + e);
        float m = lg[0];
        #pragma unroll
        for (int e = 1; e < NEXP; e++) m = fmaxf(m, lg[e]);
        float p[NEXP], s = 0.f;
        #pragma unroll
        for (int e = 0; e < NEXP; e++) { p[e] = expf(lg[e] - m); s += p[e]; }
        const float inv = 1.f / s;
        int i1 = 0;
        #pragma unroll
        for (int e = 1; e < NEXP; e++) if (lg[e] > lg[i1]) i1 = e;
        int i2 = (i1 == 0) ? 1 : 0;
        #pragma unroll
        for (int e = 0; e < NEXP; e++) if (e != i1 && lg[e] > lg[i2]) i2 = e;

        float g[NEXP];
        float* gm = (float*)(smem + OFF_GM);
        #pragma unroll
        for (int e = 0; e < NEXP; e++) {
            g[e] = p[e] * inv;
            gm[row * NEXP + e] = (e == i1 || e == i2) ? g[e] : 0.f;
        }
        uint32_t* ag = (uint32_t*)(smem + OFF_AG + row * (LDS_AG * 2));
        ag[0] = packh2(g[0], g[1]);
        ag[1] = packh2(g[2], g[3]);
        ag[2] = packh2(g[4], g[5]);
        ag[3] = packh2(g[6], g[7]);
        ag[4] = 0; ag[5] = 0; ag[6] = 0; ag[7] = 0;
    }
    __syncthreads();

    // ---- compute: warp tiling 4(m) x 2(n); warp tile 32 x 64 ----
    const int mb = (wid >> 1) * 32;
    const int nb = (wid & 1) * 64;
    const int arow = lane & 15;                 // ldmatrix A row-in-tile
    const int acb  = (lane >> 4) * 8;           // A k-block (halves)
    const int brow = ((lane >> 4) & 1) * 8 + (lane & 7);   // ldmatrix B row select
    const int bcol = ((lane >> 3) & 1) * 8;                // B k-block (halves)

    float acc[2][8][4];
    #pragma unroll
    for (int t = 0; t < 2; t++)
        #pragma unroll
        for (int j = 0; j < 8; j++)
            #pragma unroll
            for (int q = 0; q < 4; q++) acc[t][j][q] = 0.f;

    // ---- bias GEMM step: D += gates_full @ b ----
    {
        uint32_t at[2][4];
        #pragma unroll
        for (int t = 0; t < 2; t++) {
            uint32_t addr = sb + OFF_AG + (uint32_t)((mb + t * 16 + arow) * (LDS_AG * 2) + acb * 2);
            LDSM_X4(at[t][0], at[t][1], at[t][2], at[t][3], addr);
        }
        #pragma unroll
        for (int jp = 0; jp < 4; jp++) {
            uint32_t b0, b1, b2, b3;
            uint32_t addr = sb + OFF_BG + (uint32_t)((nb + jp * 16 + brow) * (LDS_AG * 2) + bcol * 2);
            LDSM_X4(b0, b1, b2, b3, addr);
            #pragma unroll
            for (int t = 0; t < 2; t++) {
                MMA_16816(acc[t][2 * jp],     at[t], b0, b1);
                MMA_16816(acc[t][2 * jp + 1], at[t], b2, b3);
            }
        }
    }

    // W_0 must be resident before expert 0 compute
    CP_WAIT0();
    __syncthreads();

    // ---- expert loop ----
    const float* gm = (const float*)(smem + OFF_GM);
    for (int e = 0; e < NEXP; e++) {
        // per-row masked gates as duplicated f16x2 (rows g and g+8 of each m16 tile)
        uint32_t gl[2], gh[2];
        #pragma unroll
        for (int t = 0; t < 2; t++) {
            const int r0 = mb + t * 16 + (lane >> 2);
            gl[t] = f2h2dup(gm[r0 * NEXP + e]);
            gh[t] = f2h2dup(gm[(r0 + 8) * NEXP + e]);
        }

        #pragma unroll
        for (int ks = 0; ks < 8; ks++) {
            uint32_t at[2][4];
            #pragma unroll
            for (int t = 0; t < 2; t++) {
                uint32_t addr = sb + OFF_XH +
                    (uint32_t)((mb + t * 16 + arow) * LDHB + ks * 32 + acb * 2);
                LDSM_X4(at[t][0], at[t][1], at[t][2], at[t][3], addr);
                at[t][0] = hmul2(at[t][0], gl[t]);
                at[t][2] = hmul2(at[t][2], gl[t]);
                at[t][1] = hmul2(at[t][1], gh[t]);
                at[t][3] = hmul2(at[t][3], gh[t]);
            }
            #pragma unroll
            for (int jp = 0; jp < 4; jp++) {
                uint32_t b0, b1, b2, b3;
                uint32_t addr = sb + OFF_WH +
                    (uint32_t)((nb + jp * 16 + brow) * LDHB + ks * 32 + bcol * 2);
                LDSM_X4(b0, b1, b2, b3, addr);
                #pragma unroll
                for (int t = 0; t < 2; t++) {
                    MMA_16816(acc[t][2 * jp],     at[t], b0, b1);
                    MMA_16816(acc[t][2 * jp + 1], at[t], b2, b3);
                }
            }
        }

        __syncthreads();        // all warps done reading W_e
        if (e < NEXP - 1) {
            const char* src = (const char*)g_Wh + (size_t)(e + 1) * DIM * DIM * 2;
            #pragma unroll
            for (int it = 0; it < 8; it++) {
                const int c = tid + it * TPB;
                const uint32_t dst = sb + OFF_WH + (uint32_t)((c >> 4) * LDHB + (c & 15) * 16);
                CP_ASYNC16(dst, src + c * 16);
            }
            CP_COMMIT();
            CP_WAIT0();
            __syncthreads();    // W_{e+1} visible to all warps
        }
    }

    // ---- store C fragments directly (bias already folded in) ----
    #pragma unroll
    for (int t = 0; t < 2; t++) {
        const long r0 = tbase + mb + t * 16 + (lane >> 2);
        #pragma unroll
        for (int j = 0; j < 8; j++) {
            const int col = nb + j * 8 + (lane & 3) * 2;
            float2 v01 = make_float2(acc[t][j][0], acc[t][j][1]);
            float2 v23 = make_float2(acc[t][j][2], acc[t][j][3]);
            *(float2*)(out + r0 * DIM + col)       = v01;
            *(float2*)(out + (r0 + 8) * DIM + col) = v23;
        }
    }
}

// ---------------- launch ----------------

extern "C" void kernel_launch(void* const* d_in, const int* in_sizes, int n_in,
                              void* d_out, int out_size)
{
    const float* x  = (const float*)d_in[0];
    const float* gW = (const float*)d_in[1];
    const float* gb = (const float*)d_in[2];
    const float* W  = (const float*)d_in[3];
    const float* b  = (const float*)d_in[4];
    float* out = (float*)d_out;

    const int rows = in_sizes[0] / DIM;      // 524288 tokens
    const int grid = rows / TILE_M;          // 4096 CTAs

    convert_w_kernel<<<NEXP * DIM * DIM / 4 / 256, 256>>>(W);

    cudaFuncSetAttribute(moe_f16_kernel,
                         cudaFuncAttributeMaxDynamicSharedMemorySize, SMEM_BYTES);
    moe_f16_kernel<<<grid, TPB, SMEM_BYTES>>>(x, gW, gb, b, out);
}